// round 4
// baseline (speedup 1.0000x reference)
#include <cuda_runtime.h>
#include <math.h>

// Problem constants
#define NB    4
#define NLQ   1024
#define NC    256
#define NH    8
#define NDH   32
#define NL    4
#define NP    4
#define NDFF  1024
#define NLSRC 21760

// Scratch layout (floats)
#define OFF_QK   0ll
#define OFF_Q    (1ll*1048576)
#define OFF_K    (2ll*1048576)
#define OFF_V    (3ll*1048576)
#define OFF_ATT  (4ll*1048576)
#define OFF_TMP  (5ll*1048576)
#define OFF_TGT1 (6ll*1048576)
#define OFF_X    (7ll*1048576)
#define OFF_OFFS (8ll*1048576)
#define OFF_AW   (9ll*1048576)
#define OFF_SAMP (10ll*1048576)
#define OFF_TGT2 (11ll*1048576)
#define OFF_FFN1 (12ll*1048576)           // 4M floats
#define OFF_VAL  (16ll*1048576)           // 22282240 floats
#define OFF_SC   (OFF_VAL + 22282240ll)   // 33554432 floats
#define SCRATCH_TOTAL (OFF_SC + 33554432ll)

__device__ float g_scratch[SCRATCH_TOTAL];

// ---------------- elementwise add ----------------
__global__ void add_k(const float* __restrict__ a, const float* __restrict__ b,
                      float* __restrict__ o, int n) {
    int i = blockIdx.x * blockDim.x + threadIdx.x;
    if (i < n) o[i] = a[i] + b[i];
}

// ---------------- block reduce helpers (256 threads) ----------------
__device__ __forceinline__ float blockSum256(float v, float* sm) {
    #pragma unroll
    for (int o = 16; o > 0; o >>= 1) v += __shfl_xor_sync(0xffffffffu, v, o);
    __syncthreads();
    if ((threadIdx.x & 31) == 0) sm[threadIdx.x >> 5] = v;
    __syncthreads();
    return sm[0] + sm[1] + sm[2] + sm[3] + sm[4] + sm[5] + sm[6] + sm[7];
}
__device__ __forceinline__ float blockMax256(float v, float* sm) {
    #pragma unroll
    for (int o = 16; o > 0; o >>= 1) v = fmaxf(v, __shfl_xor_sync(0xffffffffu, v, o));
    __syncthreads();
    if ((threadIdx.x & 31) == 0) sm[threadIdx.x >> 5] = v;
    __syncthreads();
    float r = sm[0];
    #pragma unroll
    for (int i = 1; i < 8; i++) r = fmaxf(r, sm[i]);
    return r;
}

// ---------------- generic tiled GEMM ----------------
// C = alpha * A @ op(B) + bias, optional relu.
// TRANSB: B is [N,K] row-major (weights). !TRANSB: B is [K,N] row-major.
// Batched via blockIdx.z with two-level offset: z -> (z/zdiv, z%zdiv).
// BK must be 16. No bounds checks: M%BM==0, N%BN==0, K%BK==0 guaranteed by caller.
template<int BM, int BN, int TM, int TN, bool TRANSB, bool RELU>
__global__ void __launch_bounds__(256, 2)
gemm_k(const float* __restrict__ A, const float* __restrict__ Bm,
       const float* __restrict__ bias, float* __restrict__ C,
       int K, int lda, int ldb, int ldc,
       int zdiv, long sA0, long sA1, long sB0, long sB1, long sC0, long sC1,
       float alpha)
{
    const int BK = 16;
    __shared__ float As[16][BM + 4];
    __shared__ float Bs[16][BN + 4];

    const int z = blockIdx.z;
    const long zo = z / zdiv, zi = z % zdiv;
    A  += zo * sA0 + zi * sA1;
    Bm += zo * sB0 + zi * sB1;
    C  += zo * sC0 + zi * sC1;

    const int m0 = blockIdx.x * BM;
    const int n0 = blockIdx.y * BN;
    const int t  = threadIdx.x;
    const int tx = t & 15, ty = t >> 4;

    float acc[TM][TN];
    #pragma unroll
    for (int i = 0; i < TM; i++)
        #pragma unroll
        for (int j = 0; j < TN; j++) acc[i][j] = 0.f;

    for (int k0 = 0; k0 < K; k0 += BK) {
        #pragma unroll
        for (int i = 0; i < (BM * BK) / 256; i++) {
            int idx = t + i * 256;
            int r = idx >> 4, c = idx & 15;
            As[c][r] = A[(long)(m0 + r) * lda + (k0 + c)];
        }
        if (TRANSB) {
            #pragma unroll
            for (int i = 0; i < (BN * BK) / 256; i++) {
                int idx = t + i * 256;
                int r = idx >> 4, c = idx & 15;
                Bs[c][r] = Bm[(long)(n0 + r) * ldb + (k0 + c)];
            }
        } else {
            #pragma unroll
            for (int i = 0; i < (BN * BK) / 256; i++) {
                int idx = t + i * 256;
                int kk = idx / BN, nn = idx % BN;
                Bs[kk][nn] = Bm[(long)(k0 + kk) * ldb + (n0 + nn)];
            }
        }
        __syncthreads();
        #pragma unroll
        for (int kk = 0; kk < BK; kk++) {
            float a[TM], b[TN];
            #pragma unroll
            for (int i = 0; i < TM; i++) a[i] = As[kk][ty * TM + i];
            #pragma unroll
            for (int j = 0; j < TN; j++) b[j] = Bs[kk][tx * TN + j];
            #pragma unroll
            for (int i = 0; i < TM; i++)
                #pragma unroll
                for (int j = 0; j < TN; j++) acc[i][j] = fmaf(a[i], b[j], acc[i][j]);
        }
        __syncthreads();
    }

    #pragma unroll
    for (int i = 0; i < TM; i++) {
        long rowoff = (long)(m0 + ty * TM + i) * ldc + n0;
        #pragma unroll
        for (int j = 0; j < TN; j++) {
            float v = acc[i][j] * alpha;
            if (bias) v += bias[n0 + tx * TN + j];
            if (RELU) v = fmaxf(v, 0.f);
            C[rowoff + tx * TN + j] = v;
        }
    }
}

// ---------------- row softmax over 1024-wide rows ----------------
__global__ void softmax_k(float* __restrict__ S) {
    __shared__ float sm[8];
    float* row = S + (long)blockIdx.x * 1024;
    int t = threadIdx.x;
    float v[4];
    float mx = -3.4e38f;
    #pragma unroll
    for (int i = 0; i < 4; i++) { v[i] = row[t + i * 256]; mx = fmaxf(mx, v[i]); }
    mx = blockMax256(mx, sm);
    float s = 0.f;
    #pragma unroll
    for (int i = 0; i < 4; i++) { v[i] = __expf(v[i] - mx); s += v[i]; }
    s = blockSum256(s, sm);
    float inv = 1.f / s;
    #pragma unroll
    for (int i = 0; i < 4; i++) row[t + i * 256] = v[i] * inv;
}

// ---------------- residual + layernorm (+ optional out2 = ln + pos) ----------------
__global__ void resln_k(const float* __restrict__ a, const float* __restrict__ b,
                        const float* __restrict__ g, const float* __restrict__ be,
                        float* __restrict__ out,
                        const float* __restrict__ pos, float* __restrict__ out2)
{
    __shared__ float sm[8];
    int row = blockIdx.x, t = threadIdx.x;
    long off = (long)row * NC + t;
    float x = a[off] + b[off];
    float m = blockSum256(x, sm) * (1.f / NC);
    float d = x - m;
    float v = blockSum256(d * d, sm) * (1.f / NC);
    float y = d * rsqrtf(v + 1e-5f) * g[t] + be[t];
    out[off] = y;
    if (out2) out2[off] = y + pos[off];
}

// ---------------- deformable sampling (one warp per (b,q,h), lanes = DH) ----------------
__global__ void deform_k(const float* __restrict__ value,
                         const float* __restrict__ offs,
                         const float* __restrict__ awl,
                         const float* __restrict__ refp,
                         float* __restrict__ out)
{
    int gw   = (blockIdx.x * blockDim.x + threadIdx.x) >> 5;
    int lane = threadIdx.x & 31;
    int h  = gw & 7;
    int bq = gw >> 3;           // b*LQ + q
    int b  = bq >> 10;

    // attention-weight softmax over L*P = 16 logits (warp-uniform redundant compute)
    const float* ap = awl + ((long)bq * NH + h) * 16;
    float w[16];
    float mx = -3.4e38f;
    #pragma unroll
    for (int j = 0; j < 16; j++) { w[j] = ap[j]; mx = fmaxf(mx, w[j]); }
    float s = 0.f;
    #pragma unroll
    for (int j = 0; j < 16; j++) { w[j] = __expf(w[j] - mx); s += w[j]; }
    float inv = 1.f / s;

    const float* op = offs + ((long)bq * NH + h) * 32;   // L*P*2 per (b,q,h)
    const float* rp = refp + (long)bq * 8;               // L*2 per (b,q)
    const float* vb = value + (long)b * NLSRC * NC + h * NDH + lane;

    const int wl_[4] = {128, 64, 32, 16};
    const int st_[4] = {0, 16384, 20480, 21504};

    float acc = 0.f;
    #pragma unroll
    for (int l = 0; l < 4; l++) {
        const int W = wl_[l], Hh = wl_[l];
        const int st = st_[l];
        // loc*W - 0.5 = ref*W + off - 0.5   (offsets normalized by (W,H) then rescaled)
        float rx = rp[l * 2 + 0] * (float)W  - 0.5f;
        float ry = rp[l * 2 + 1] * (float)Hh - 0.5f;
        #pragma unroll
        for (int p = 0; p < 4; p++) {
            float a = w[l * 4 + p] * inv;
            float x = rx + op[(l * 4 + p) * 2 + 0];
            float y = ry + op[(l * 4 + p) * 2 + 1];
            float xf = floorf(x), yf = floorf(y);
            int x0 = (int)xf, y0 = (int)yf;
            float wx1 = x - xf, wy1 = y - yf;
            float wx0 = 1.f - wx1, wy0 = 1.f - wy1;
            #pragma unroll
            for (int cy = 0; cy < 2; cy++) {
                int iy = y0 + cy;
                if (iy < 0 || iy >= Hh) continue;       // zero-padding: skip
                float wy = cy ? wy1 : wy0;
                #pragma unroll
                for (int cx = 0; cx < 2; cx++) {
                    int ix = x0 + cx;
                    if (ix < 0 || ix >= W) continue;
                    float cw = a * wy * (cx ? wx1 : wx0);
                    acc += cw * vb[(long)(st + iy * W + ix) * NC];
                }
            }
        }
    }
    out[(long)bq * NC + h * NDH + lane] = acc;
}

extern "C" void kernel_launch(void* const* d_in, const int* in_sizes, int n_in,
                              void* d_out, int out_size)
{
    const float* tgt   = (const float*)d_in[0];
    const float* qpos  = (const float*)d_in[1];
    const float* refp  = (const float*)d_in[2];
    const float* src   = (const float*)d_in[3];
    const float* in_w  = (const float*)d_in[4];
    const float* in_b  = (const float*)d_in[5];
    const float* sa_w  = (const float*)d_in[6];
    const float* sa_b  = (const float*)d_in[7];
    const float* off_w = (const float*)d_in[8];
    const float* off_b = (const float*)d_in[9];
    const float* aw_w  = (const float*)d_in[10];
    const float* aw_b  = (const float*)d_in[11];
    const float* val_w = (const float*)d_in[12];
    const float* val_b = (const float*)d_in[13];
    const float* co_w  = (const float*)d_in[14];
    const float* co_b  = (const float*)d_in[15];
    const float* ln1_g = (const float*)d_in[16];
    const float* ln1_b = (const float*)d_in[17];
    const float* ln2_g = (const float*)d_in[18];
    const float* ln2_b = (const float*)d_in[19];
    const float* ln3_g = (const float*)d_in[20];
    const float* ln3_b = (const float*)d_in[21];
    const float* f1_w  = (const float*)d_in[22];
    const float* f1_b  = (const float*)d_in[23];
    const float* f2_w  = (const float*)d_in[24];
    const float* f2_b  = (const float*)d_in[25];

    float* S = nullptr;
    cudaGetSymbolAddress((void**)&S, g_scratch);

    float* qk    = S + OFF_QK;
    float* qb    = S + OFF_Q;
    float* kb    = S + OFF_K;
    float* vb    = S + OFF_V;
    float* att   = S + OFF_ATT;
    float* tmp   = S + OFF_TMP;
    float* tgt1  = S + OFF_TGT1;
    float* xq    = S + OFF_X;
    float* offb  = S + OFF_OFFS;
    float* awb   = S + OFF_AW;
    float* samp  = S + OFF_SAMP;
    float* tgt2  = S + OFF_TGT2;
    float* ffn1  = S + OFF_FFN1;
    float* valb  = S + OFF_VAL;
    float* sc    = S + OFF_SC;

    const float scale = 0.1767766952966369f; // 1/sqrt(32)

    // ---- self-attention ----
    add_k<<<4096, 256>>>(tgt, qpos, qk, NB * NLQ * NC);

    // q,k,v projections  (M=4096, N=256, K=256)
    gemm_k<128,64,8,4,true,false><<<dim3(32,4,1), 256>>>(qk,  in_w,          in_b,       qb, 256, 256,256,256, 1,0,0,0,0,0,0, 1.f);
    gemm_k<128,64,8,4,true,false><<<dim3(32,4,1), 256>>>(qk,  in_w + 65536,  in_b + 256, kb, 256, 256,256,256, 1,0,0,0,0,0,0, 1.f);
    gemm_k<128,64,8,4,true,false><<<dim3(32,4,1), 256>>>(tgt, in_w + 131072, in_b + 512, vb, 256, 256,256,256, 1,0,0,0,0,0,0, 1.f);

    // scores[b,h] = scale * Q K^T    (M=N=1024, K=32, batch 32, z = b*8+h)
    gemm_k<128,64,8,4,true,false><<<dim3(8,16,32), 256>>>(
        qb, kb, nullptr, sc, 32, 256, 256, 1024,
        8, 262144ll, 32ll, 262144ll, 32ll, 8388608ll, 1048576ll, scale);

    softmax_k<<<32768, 256>>>(sc);

    // O[b,h] = P @ V    (M=1024, N=32, K=1024, B is [K,N] slice of vb)
    gemm_k<64,32,4,2,false,false><<<dim3(16,1,32), 256>>>(
        sc, vb, nullptr, att, 1024, 1024, 256, 256,
        8, 8388608ll, 1048576ll, 262144ll, 32ll, 262144ll, 32ll, 1.f);

    // out projection + residual + LN2 (and x = ln_out + pos)
    gemm_k<128,64,8,4,true,false><<<dim3(32,4,1), 256>>>(att, sa_w, sa_b, tmp, 256, 256,256,256, 1,0,0,0,0,0,0, 1.f);
    resln_k<<<4096, 256>>>(tgt, tmp, ln2_g, ln2_b, tgt1, qpos, xq);

    // ---- deformable cross-attention ----
    // value = src @ val_w^T + val_b   (M=87040)
    gemm_k<128,64,8,4,true,false><<<dim3(680,4,1), 256>>>(src, val_w, val_b, valb, 256, 256,256,256, 1,0,0,0,0,0,0, 1.f);
    // offsets and attention-weight logits
    gemm_k<128,64,8,4,true,false><<<dim3(32,4,1), 256>>>(xq, off_w, off_b, offb, 256, 256,256,256, 1,0,0,0,0,0,0, 1.f);
    gemm_k<128,64,8,4,true,false><<<dim3(32,2,1), 256>>>(xq, aw_w,  aw_b,  awb,  256, 256,256,128, 1,0,0,0,0,0,0, 1.f);

    deform_k<<<4096, 256>>>(valb, offb, awb, refp, samp);

    gemm_k<128,64,8,4,true,false><<<dim3(32,4,1), 256>>>(samp, co_w, co_b, tmp, 256, 256,256,256, 1,0,0,0,0,0,0, 1.f);
    resln_k<<<4096, 256>>>(tgt1, tmp, ln1_g, ln1_b, tgt2, nullptr, nullptr);

    // ---- FFN ----
    gemm_k<128,64,8,4,true,true ><<<dim3(32,16,1), 256>>>(tgt2, f1_w, f1_b, ffn1, 256,  256, 256, 1024, 1,0,0,0,0,0,0, 1.f);
    gemm_k<128,64,8,4,true,false><<<dim3(32,4,1),  256>>>(ffn1, f2_w, f2_b, tmp,  1024, 1024,1024, 256, 1,0,0,0,0,0,0, 1.f);
    resln_k<<<4096, 256>>>(tgt2, tmp, ln3_g, ln3_b, (float*)d_out, nullptr, nullptr);
}